// round 4
// baseline (speedup 1.0000x reference)
#include <cuda_runtime.h>
#include <cuda_bf16.h>
#include <cstdint>

// LSTM: B=4096, T=2048, I=1, H=8, then FC [H]->[4].
// R4: back to 8 lanes/batch, 4 batches/warp (1024 warps) -> only 2 shfl per
// batch-step (8 per warp-step, no gate exchange), unclogging the MIO/shfl
// pipe that bound R3 (L1=52.7%). Latency exposure at 1.73 warps/SMSP is cut
// by tanh.approx activations (single-MUFU) and dual-accumulator FMA trees
// (gate dot chain 32 -> 20 cyc). sigmoid(z) = 0.5*tanh(z/2)+0.5 with the 0.5
// prescale folded into register-resident weights.

#define B_TOTAL 4096
#define T_STEPS 2048

__device__ __forceinline__ float tanhf_mufu(float x) {
    float r; asm("tanh.approx.f32 %0, %1;" : "=f"(r) : "f"(x)); return r;
}

__global__ __launch_bounds__(32, 32)
void lstm_fused_kernel(const float* __restrict__ x,
                       const float* __restrict__ w_ih,
                       const float* __restrict__ w_hh,
                       const float* __restrict__ b_ih,
                       const float* __restrict__ b_hh,
                       const float* __restrict__ w_fc,
                       const float* __restrict__ b_fc,
                       float* __restrict__ out)
{
    const int tid = blockIdx.x * blockDim.x + threadIdx.x;
    const int b   = tid >> 3;   // batch index (8 lanes per batch)
    const int u   = tid & 7;    // hidden unit owned by this lane

    // PyTorch gate rows: i=[0,8), f=[8,16), g=[16,24), o=[24,32).
    // Scales: i,f,o -> 0.5 (sigmoid via tanh(z/2)); g -> 1.0 (tanh direct).
    float wh[4][8], wx[4], bb[4];
    {
        const float scale[4] = { 0.5f, 0.5f, 1.0f, 0.5f };
#pragma unroll
        for (int t = 0; t < 4; t++) {
            const int row = t * 8 + u;
            const float s = scale[t];
            wx[t] = s * w_ih[row];
            bb[t] = s * (b_ih[row] + b_hh[row]);
#pragma unroll
            for (int j = 0; j < 8; j++)
                wh[t][j] = s * w_hh[row * 8 + j];
        }
    }

    float h = 0.0f, c = 0.0f;

    const float4* xb = reinterpret_cast<const float4*>(x + (size_t)b * T_STEPS);
    float4 xv = xb[0];

    for (int t4 = 0; t4 < T_STEPS / 4; t4++) {
        float4 xnext;
        if (t4 + 1 < T_STEPS / 4) xnext = xb[t4 + 1];

        const float xs[4] = { xv.x, xv.y, xv.z, xv.w };
#pragma unroll
        for (int k = 0; k < 4; k++) {
            const float xt = xs[k];

            // x-term pre-muls (off the h critical path; issue while shfls fly)
            float xw0 = xt * wx[0];
            float xw1 = xt * wx[1];
            float xw2 = xt * wx[2];
            float xw3 = xt * wx[3];

            // Broadcast all 8 h values (independent shfls, issued back-to-back)
            float hj[8];
#pragma unroll
            for (int j = 0; j < 8; j++)
                hj[j] = __shfl_sync(0xffffffffu, h, j, 8);

            // Dual-accumulator trees: even chain seeded with bias, odd with x-term.
            float a[4];
#pragma unroll
            for (int g = 0; g < 4; g++) {
                float e = fmaf(hj[6], wh[g][6], bb[g]);
                float o = fmaf(hj[7], wh[g][7], (g == 0) ? xw0 : (g == 1) ? xw1 : (g == 2) ? xw2 : xw3);
                e = fmaf(hj[4], wh[g][4], e);
                o = fmaf(hj[5], wh[g][5], o);
                e = fmaf(hj[2], wh[g][2], e);
                o = fmaf(hj[3], wh[g][3], o);
                e = fmaf(hj[0], wh[g][0], e);
                o = fmaf(hj[1], wh[g][1], o);
                a[g] = e + o;
            }

            const float ti = tanhf_mufu(a[0]);
            const float tf = tanhf_mufu(a[1]);
            const float tg = tanhf_mufu(a[2]);   // tanh gate, full scale
            const float to = tanhf_mufu(a[3]);

            const float iv = fmaf(0.5f, ti, 0.5f);
            const float fv = fmaf(0.5f, tf, 0.5f);
            const float ov = fmaf(0.5f, to, 0.5f);

            c = fmaf(fv, c, iv * tg);
            const float tc = tanhf_mufu(c);
            h = ov * tc;
        }
        xv = xnext;
    }

    // FC head: out[b][k] = b_fc[k] + sum_u h_u * w_fc[k*8 + u]
    float p0 = h * w_fc[0 * 8 + u];
    float p1 = h * w_fc[1 * 8 + u];
    float p2 = h * w_fc[2 * 8 + u];
    float p3 = h * w_fc[3 * 8 + u];
#pragma unroll
    for (int off = 4; off >= 1; off >>= 1) {
        p0 += __shfl_xor_sync(0xffffffffu, p0, off, 8);
        p1 += __shfl_xor_sync(0xffffffffu, p1, off, 8);
        p2 += __shfl_xor_sync(0xffffffffu, p2, off, 8);
        p3 += __shfl_xor_sync(0xffffffffu, p3, off, 8);
    }
    if (u < 4) {
        const float pk = (u == 0) ? p0 : (u == 1) ? p1 : (u == 2) ? p2 : p3;
        out[b * 4 + u] = pk + b_fc[u];
    }
}

extern "C" void kernel_launch(void* const* d_in, const int* in_sizes, int n_in,
                              void* d_out, int out_size)
{
    const float* x    = (const float*)d_in[0];
    const float* w_ih = (const float*)d_in[1];
    const float* w_hh = (const float*)d_in[2];
    const float* b_ih = (const float*)d_in[3];
    const float* b_hh = (const float*)d_in[4];
    const float* w_fc = (const float*)d_in[5];
    const float* b_fc = (const float*)d_in[6];
    float* out = (float*)d_out;

    // 8 lanes per batch -> 32768 threads = 1024 warps.
    const int threads = 32;
    const int blocks  = (B_TOTAL * 8) / threads;
    lstm_fused_kernel<<<blocks, threads>>>(x, w_ih, w_hh, b_ih, b_hh, w_fc, b_fc, out);
}

// round 5
// speedup vs baseline: 1.0576x; 1.0576x over previous
#include <cuda_runtime.h>
#include <cuda_bf16.h>
#include <cstdint>

// LSTM: B=4096, T=2048, I=1, H=8, then FC [H]->[4].
// R5: 16 lanes/batch, 2 batches/warp, 2048 warps (3.46/SMSP for latency
// hiding). Lower 8 lanes own gates (i,g); upper 8 lanes own (f,o) AND the
// (c,h) state. h is broadcast through double-buffered shared memory
// (STS + BAR + 2x LDS.128) instead of 8 shfls; the only shfl per step is the
// xor-8 exchange of m = i*g to the upper half. Activations via MUFU.TANH
// (sigmoid(z) = 0.5*tanh(z/2)+0.5, prescale folded into weights).

#define B_TOTAL 4096
#define T_STEPS 2048
#define NT4     (T_STEPS / 4)

__device__ __forceinline__ float tanhf_mufu(float x) {
    float r; asm("tanh.approx.f32 %0, %1;" : "=f"(r) : "f"(x)); return r;
}

__global__ __launch_bounds__(32, 32)
void lstm_fused_kernel(const float* __restrict__ x,
                       const float* __restrict__ w_ih,
                       const float* __restrict__ w_hh,
                       const float* __restrict__ b_ih,
                       const float* __restrict__ b_hh,
                       const float* __restrict__ w_fc,
                       const float* __restrict__ b_fc,
                       float* __restrict__ out)
{
    // [parity][group][half-of-8-floats]; one warp per block, 2 groups of 16.
    __shared__ float4 hbuf[2][2][2];

    const int tid  = blockIdx.x * 32 + threadIdx.x;
    const int lane = threadIdx.x & 31;
    const int grp  = lane >> 4;        // which 16-lane group in the warp
    const int l    = lane & 15;        // lane within group
    const int u    = l & 7;            // hidden unit owned by this lane
    const bool hi  = (l >= 8);         // upper half owns (f,o) and (c,h)
    const int b    = tid >> 4;         // batch index

    // PyTorch gate rows: i=[0,8), f=[8,16), g=[16,24), o=[24,32).
    // Gate A: lower->i, upper->f (both sigmoid, prescale 0.5).
    // Gate B: lower->g (tanh, scale 1), upper->o (sigmoid, prescale 0.5).
    const int   rowA = hi ? (8 + u)  : u;
    const int   rowB = hi ? (24 + u) : (16 + u);
    const float sA   = 0.5f;
    const float sB   = hi ? 0.5f : 1.0f;
    const float alB  = hi ? 0.5f : 1.0f;   // gateB = alB * tanh + beB
    const float beB  = hi ? 0.5f : 0.0f;

    float whA[8], whB[8];
    float wxA, wxB, bbA, bbB;
    {
        wxA = sA * w_ih[rowA];
        wxB = sB * w_ih[rowB];
        bbA = sA * (b_ih[rowA] + b_hh[rowA]);
        bbB = sB * (b_ih[rowB] + b_hh[rowB]);
#pragma unroll
        for (int j = 0; j < 8; j++) {
            whA[j] = sA * w_hh[rowA * 8 + j];
            whB[j] = sB * w_hh[rowB * 8 + j];
        }
    }

    float h = 0.0f, c = 0.0f;   // valid in upper half only

    const float4* xb = reinterpret_cast<const float4*>(x + (size_t)b * T_STEPS);
    float4 xv = xb[0];

    float* hs[2] = { reinterpret_cast<float*>(&hbuf[0][grp][0]),
                     reinterpret_cast<float*>(&hbuf[1][grp][0]) };

    for (int t4 = 0; t4 < NT4; t4++) {
        // Branchless prefetch (clamped index -> IMNMX + LDG, no BSSY/BSYNC).
        const int nx = (t4 + 1 < NT4) ? (t4 + 1) : t4;
        const float4 xnext = xb[nx];

        const float xs[4] = { xv.x, xv.y, xv.z, xv.w };
#pragma unroll
        for (int k = 0; k < 4; k++) {
            const int p = k & 1;               // step parity (double buffer)
            float* hw = hs[p];

            if (hi) hw[u] = h;                 // upper half publishes h
            __syncthreads();                   // 1-warp block: cheap BAR + fence

            const float4 ha = reinterpret_cast<const float4*>(hw)[0];
            const float4 hb = reinterpret_cast<const float4*>(hw)[1];

            const float xt  = xs[k];
            const float xwA = xt * wxA;
            const float xwB = xt * wxB;

            // Dual-accumulator trees (depth 4) per gate.
            float eA = fmaf(ha.z, whA[2], bbA);
            float oA = fmaf(ha.w, whA[3], xwA);
            float eB = fmaf(ha.z, whB[2], bbB);
            float oB = fmaf(ha.w, whB[3], xwB);
            eA = fmaf(ha.x, whA[0], eA);  oA = fmaf(ha.y, whA[1], oA);
            eB = fmaf(ha.x, whB[0], eB);  oB = fmaf(ha.y, whB[1], oB);
            eA = fmaf(hb.x, whA[4], eA);  oA = fmaf(hb.y, whA[5], oA);
            eB = fmaf(hb.x, whB[4], eB);  oB = fmaf(hb.y, whB[5], oB);
            eA = fmaf(hb.z, whA[6], eA);  oA = fmaf(hb.w, whA[7], oA);
            eB = fmaf(hb.z, whB[6], eB);  oB = fmaf(hb.w, whB[7], oB);
            const float aA = eA + oA;
            const float aB = eB + oB;

            const float tA = tanhf_mufu(aA);
            const float tB = tanhf_mufu(aB);
            const float rA = fmaf(0.5f, tA, 0.5f);   // i (lo) / f (hi)
            const float gB = fmaf(alB,  tB, beB);    // g (lo) / o (hi)

            // lower computes m = i*g; xor-8 sends it to the upper half.
            const float m   = rA * gB;
            const float m_u = __shfl_xor_sync(0xffffffffu, m, 8, 16);

            c = fmaf(rA, c, m_u);                    // f*c + i*g  (upper valid)
            const float tc = tanhf_mufu(c);
            h = gB * tc;                             // o * tanh(c) (upper valid)
        }
        xv = xnext;
    }

    // FC head: out[b][k] = b_fc[k] + sum_u h_u * w_fc[k*8 + u]
    // h valid in upper 8 lanes; width-8 xor reduction stays within {8..15}.
    float p0 = h * w_fc[0 * 8 + u];
    float p1 = h * w_fc[1 * 8 + u];
    float p2 = h * w_fc[2 * 8 + u];
    float p3 = h * w_fc[3 * 8 + u];
#pragma unroll
    for (int off = 4; off >= 1; off >>= 1) {
        p0 += __shfl_xor_sync(0xffffffffu, p0, off, 8);
        p1 += __shfl_xor_sync(0xffffffffu, p1, off, 8);
        p2 += __shfl_xor_sync(0xffffffffu, p2, off, 8);
        p3 += __shfl_xor_sync(0xffffffffu, p3, off, 8);
    }
    if (hi && (l & 7) < 4) {
        const int kk = l & 7;
        const float pk = (kk == 0) ? p0 : (kk == 1) ? p1 : (kk == 2) ? p2 : p3;
        out[b * 4 + kk] = pk + b_fc[kk];
    }
}

extern "C" void kernel_launch(void* const* d_in, const int* in_sizes, int n_in,
                              void* d_out, int out_size)
{
    const float* x    = (const float*)d_in[0];
    const float* w_ih = (const float*)d_in[1];
    const float* w_hh = (const float*)d_in[2];
    const float* b_ih = (const float*)d_in[3];
    const float* b_hh = (const float*)d_in[4];
    const float* w_fc = (const float*)d_in[5];
    const float* b_fc = (const float*)d_in[6];
    float* out = (float*)d_out;

    // 16 lanes per batch -> 65536 threads = 2048 warps (one warp per block).
    const int threads = 32;
    const int blocks  = (B_TOTAL * 16) / threads;
    lstm_fused_kernel<<<blocks, threads>>>(x, w_ih, w_hh, b_ih, b_hh, w_fc, b_fc, out);
}